// round 16
// baseline (speedup 1.0000x reference)
#include <cuda_runtime.h>

#define SEQ    1024
#define BATCH  2048
#define HID    64
#define NB     8        // batches per CTA
#define XCHUNK 128

__device__ __forceinline__ float tanhA(float x) {
    float y;
    asm("tanh.approx.f32 %0, %1;" : "=f"(y) : "f"(x));
    return y;
}
__device__ __forceinline__ float sigA(float x) {
    return fmaf(0.5f, tanhA(0.5f * x), 0.5f);
}
__device__ __forceinline__ unsigned cvt_tf32(float x) {
    unsigned r;
    asm("cvt.rna.tf32.f32 %0, %1;" : "=r"(r) : "f"(x));
    return r;
}
__device__ __forceinline__ void mma_tf32(float& d0, float& d1, float& d2, float& d3,
                                         unsigned a0, unsigned a1, unsigned a2, unsigned a3,
                                         unsigned b0, unsigned b1) {
    asm("mma.sync.aligned.m16n8k8.row.col.f32.tf32.tf32.f32 "
        "{%0,%1,%2,%3}, {%4,%5,%6,%7}, {%8,%9}, {%0,%1,%2,%3};"
        : "+f"(d0), "+f"(d1), "+f"(d2), "+f"(d3)
        : "r"(a0), "r"(a1), "r"(a2), "r"(a3), "r"(b0), "r"(b1));
}

// R13 (gate-major permuted tf32 mma, register-local LSTM update, 1 bar/step)
// + paired-H layout for LDS.64 B-frag loads + 3-way accumulator split + tt
// unrolled by 2 with static ping/pong H buffers.
//
// sh_H layout (per buffer, 256 words): word = kt*64 + tg*16 + n*2 + s
//   s=0 -> k-row 8kt+tg ; s=1 -> k-row 8kt+tg+4   (tg in [0,4))
// Consumer (thread gid,tig), k-tile kt: LDS.64 at kt*64+tig*16+gid*2 gives
//   (b0,b1) = (B[8kt+tig][gid], B[8kt+tig+4][gid]).
// Writer (warp w, thread gid,tig): unit u = w*8+gid -> kt=w, tg=gid&3,
//   s=gid>>2; writes n=2tig,2tig+1 at base + n*2 (two STS.32).
__global__ void __launch_bounds__(256, 2)
lstm_mma_kernel(const float* __restrict__ x,
                const float* __restrict__ W_ih,
                const float* __restrict__ W_hh,
                const float* __restrict__ b_ih,
                const float* __restrict__ b_hh,
                const float* __restrict__ fc1_w,
                const float* __restrict__ fc1_b,
                const float* __restrict__ fc2_w,
                const float* __restrict__ fc2_b,
                float* __restrict__ out)
{
    const int b0   = blockIdx.x * NB;
    const int j    = threadIdx.x;
    const int w    = j >> 5;
    const int lane = j & 31;
    const int gid  = lane >> 2;
    const int tig  = lane & 3;
    const int u    = w * 8 + gid;          // hidden unit owned by this thread

    __shared__ float sh_H[2][256];         // paired-H layout (tf32 bits)
    __shared__ float sh_x[XCHUNK * NB];    // x[tt][n]
    __shared__ float sh_c[NB][HID];
    __shared__ float sh_hd[NB][128];

    // ---- resident A fragments, gate-major permuted (same map as R13) ----
    unsigned Afr[2][8][4];
    #pragma unroll
    for (int mt = 0; mt < 2; mt++) {
        const int rLo = (2 * mt) * HID + u;        // gate 2mt   row
        const int rHi = (2 * mt + 1) * HID + u;    // gate 2mt+1 row
        #pragma unroll
        for (int kt = 0; kt < 8; kt++) {
            Afr[mt][kt][0] = cvt_tf32(__ldg(W_hh + rLo * HID + kt * 8 + tig));
            Afr[mt][kt][1] = cvt_tf32(__ldg(W_hh + rHi * HID + kt * 8 + tig));
            Afr[mt][kt][2] = cvt_tf32(__ldg(W_hh + rLo * HID + kt * 8 + tig + 4));
            Afr[mt][kt][3] = cvt_tf32(__ldg(W_hh + rHi * HID + kt * 8 + tig + 4));
        }
    }
    float wih[4], bias[4];
    #pragma unroll
    for (int g = 0; g < 4; g++) {
        const int r = g * HID + u;
        wih[g]  = __ldg(W_ih + r);
        bias[g] = __ldg(b_ih + r) + __ldg(b_hh + r);
    }

    // writer address for h (per thread): two words, n*2 apart
    const int wbase = w * 64 + (gid & 3) * 16 + (gid >> 2);
    // consumer base offset (per thread) within a buffer
    const int rbase = tig * 16 + gid * 2;

    float c0r = 0.0f, c1r = 0.0f;   // cell state, batches 2tig / 2tig+1

    for (int idx = j; idx < 256; idx += 256) sh_H[0][idx] = 0.0f;
    __syncthreads();

    // ---- one LSTM step: read Hin, write Hout ----
    auto step = [&](const float* __restrict__ Hin, float* __restrict__ Hout,
                    int tt) {
        const float2 xv = *reinterpret_cast<const float2*>(&sh_x[tt * 8 + 2 * tig]);

        float d [2][4], d2[2][4], d3[2][4];
        #pragma unroll
        for (int mt = 0; mt < 2; mt++) {
            d [mt][0] = fmaf(xv.x, wih[2 * mt],     bias[2 * mt]);
            d [mt][1] = fmaf(xv.y, wih[2 * mt],     bias[2 * mt]);
            d [mt][2] = fmaf(xv.x, wih[2 * mt + 1], bias[2 * mt + 1]);
            d [mt][3] = fmaf(xv.y, wih[2 * mt + 1], bias[2 * mt + 1]);
            d2[mt][0] = 0.0f; d2[mt][1] = 0.0f; d2[mt][2] = 0.0f; d2[mt][3] = 0.0f;
            d3[mt][0] = 0.0f; d3[mt][1] = 0.0f; d3[mt][2] = 0.0f; d3[mt][3] = 0.0f;
        }

        #pragma unroll
        for (int kt = 0; kt < 8; kt++) {
            const float2 bf = *reinterpret_cast<const float2*>(&Hin[kt * 64 + rbase]);
            const unsigned bf0 = __float_as_uint(bf.x);
            const unsigned bf1 = __float_as_uint(bf.y);
            float (*acc)[4] = (kt < 3) ? d : (kt < 6) ? d2 : d3;
            mma_tf32(acc[0][0], acc[0][1], acc[0][2], acc[0][3],
                     Afr[0][kt][0], Afr[0][kt][1], Afr[0][kt][2], Afr[0][kt][3],
                     bf0, bf1);
            mma_tf32(acc[1][0], acc[1][1], acc[1][2], acc[1][3],
                     Afr[1][kt][0], Afr[1][kt][1], Afr[1][kt][2], Afr[1][kt][3],
                     bf0, bf1);
        }

        const float iv0 = sigA (d[0][0] + d2[0][0] + d3[0][0]);
        const float iv1 = sigA (d[0][1] + d2[0][1] + d3[0][1]);
        const float fv0 = sigA (d[0][2] + d2[0][2] + d3[0][2]);
        const float fv1 = sigA (d[0][3] + d2[0][3] + d3[0][3]);
        const float gv0 = tanhA(d[1][0] + d2[1][0] + d3[1][0]);
        const float gv1 = tanhA(d[1][1] + d2[1][1] + d3[1][1]);
        const float ov0 = sigA (d[1][2] + d2[1][2] + d3[1][2]);
        const float ov1 = sigA (d[1][3] + d2[1][3] + d3[1][3]);

        c0r = fmaf(fv0, c0r, iv0 * gv0);
        c1r = fmaf(fv1, c1r, iv1 * gv1);
        const float h0 = ov0 * tanhA(c0r);
        const float h1 = ov1 * tanhA(c1r);

        Hout[wbase + (2 * tig) * 2]     = __uint_as_float(cvt_tf32(h0));
        Hout[wbase + (2 * tig + 1) * 2] = __uint_as_float(cvt_tf32(h1));
        __syncthreads();
    };

    // ---- time recurrence ----
    #pragma unroll 1
    for (int t0 = 0; t0 < SEQ; t0 += XCHUNK) {
        #pragma unroll
        for (int i = 0; i < (XCHUNK * NB) / 256; i++) {
            const int idx = j + i * 256;
            sh_x[idx] = __ldg(x + (t0 + (idx >> 3)) * BATCH + b0 + (idx & 7));
        }
        __syncthreads();

        #pragma unroll 1
        for (int tt = 0; tt < XCHUNK; tt += 2) {
            step(sh_H[0], sh_H[1], tt);
            step(sh_H[1], sh_H[0], tt + 1);
        }
    }

    // ---- MLP head on cell states (8 batches) ----
    sh_c[2 * tig][u]     = c0r;
    sh_c[2 * tig + 1][u] = c1r;
    __syncthreads();

    #pragma unroll
    for (int i = 0; i < 4; i++) {          // 8 batches x 128 rows = 1024 tasks
        const int t   = j + i * 256;
        const int row = t & 127;
        const int bt  = t >> 7;
        const float* fw = fc1_w + row * HID;
        float acc = __ldg(fc1_b + row);
        #pragma unroll
        for (int k = 0; k < HID; k++) acc = fmaf(__ldg(fw + k), sh_c[bt][k], acc);
        sh_hd[bt][row] = acc;
    }
    __syncthreads();

    if (j < NB * 5) {
        const int bt  = j / 5;
        const int row = j % 5;
        const float* fw = fc2_w + row * 128;
        float acc = __ldg(fc2_b + row);
        #pragma unroll
        for (int k = 0; k < 128; k++) acc = fmaf(__ldg(fw + k), sh_hd[bt][k], acc);
        out[(b0 + bt) * 5 + row] = acc;
    }
}

extern "C" void kernel_launch(void* const* d_in, const int* in_sizes, int n_in,
                              void* d_out, int out_size)
{
    const float* x     = (const float*)d_in[0];
    const float* W_ih  = (const float*)d_in[1];
    const float* W_hh  = (const float*)d_in[2];
    const float* b_ih  = (const float*)d_in[3];
    const float* b_hh  = (const float*)d_in[4];
    const float* fc1_w = (const float*)d_in[5];
    const float* fc1_b = (const float*)d_in[6];
    const float* fc2_w = (const float*)d_in[7];
    const float* fc2_b = (const float*)d_in[8];
    float* out = (float*)d_out;

    lstm_mma_kernel<<<BATCH / NB, 256>>>(x, W_ih, W_hh, b_ih, b_hh,
                                         fc1_w, fc1_b, fc2_w, fc2_b, out);
}

// round 17
// speedup vs baseline: 1.6472x; 1.6472x over previous
#include <cuda_runtime.h>
#include <cuda_fp16.h>

#define SEQ    1024
#define BATCH  2048
#define HID    64
#define NB     8        // batches per CTA
#define XCHUNK 128

__device__ __forceinline__ float tanhA(float x) {
    float y;
    asm("tanh.approx.f32 %0, %1;" : "=f"(y) : "f"(x));
    return y;
}
__device__ __forceinline__ float sigA(float x) {
    return fmaf(0.5f, tanhA(0.5f * x), 0.5f);
}
__device__ __forceinline__ unsigned pack_h2(float lo, float hi) {
    __half2 h = __floats2half2_rn(lo, hi);     // .x = lo half
    return *reinterpret_cast<unsigned*>(&h);
}
__device__ __forceinline__ void mma_f16(float& d0, float& d1, float& d2, float& d3,
                                        unsigned a0, unsigned a1, unsigned a2, unsigned a3,
                                        unsigned b0, unsigned b1) {
    asm("mma.sync.aligned.m16n8k16.row.col.f32.f16.f16.f32 "
        "{%0,%1,%2,%3}, {%4,%5,%6,%7}, {%8,%9}, {%0,%1,%2,%3};"
        : "+f"(d0), "+f"(d1), "+f"(d2), "+f"(d3)
        : "r"(a0), "r"(a1), "r"(a2), "r"(a3), "r"(b0), "r"(b1));
}

// fp16 m16n8k16 version of the R13 structure:
//   gate-major permuted A so each thread's D fragment holds i,f,g,o of unit
//   u = w*8+gid for batches {2tig, 2tig+1}; register-local LSTM update;
//   ONE __syncthreads per step (static ping/pong H buffers).
//
// A fragment (m16n8k16, row-major A): thread(gid,tig) holds f16x2 regs
//   a0 = A[gid][2tig,2tig+1]      a1 = A[gid+8][2tig,2tig+1]
//   a2 = A[gid][2tig+8,2tig+9]    a3 = A[gid+8][2tig+8,2tig+9]
//   (m-tile 0 rows: gate0(u) at gid / gate1(u) at gid+8; m-tile 1: gates 2,3)
// B fragment (col-major B = H[k][n]): b0 = H[2tig+16kt,+1][gid] packed,
//   b1 = H[2tig+8+16kt,+1][gid] packed.
// H smem: f16x2 word (units 2kp, 2kp+1; one batch) at word idx n*36 + kp.
//   B load: 2 conflict-free LDS.32 per k-tile (bank 4*gid+tig+8kt).
//   h store: unit pair = adjacent gid -> one shfl_xor(4) + pack + STS.32.
__global__ void __launch_bounds__(256, 2)
lstm_mma_kernel(const float* __restrict__ x,
                const float* __restrict__ W_ih,
                const float* __restrict__ W_hh,
                const float* __restrict__ b_ih,
                const float* __restrict__ b_hh,
                const float* __restrict__ fc1_w,
                const float* __restrict__ fc1_b,
                const float* __restrict__ fc2_w,
                const float* __restrict__ fc2_b,
                float* __restrict__ out)
{
    const int b0   = blockIdx.x * NB;
    const int j    = threadIdx.x;
    const int w    = j >> 5;
    const int lane = j & 31;
    const int gid  = lane >> 2;
    const int tig  = lane & 3;
    const int u    = w * 8 + gid;          // hidden unit owned by this thread

    __shared__ unsigned sh_H[2][8 * 36];   // H as f16x2 words, [n][kp] stride 36
    __shared__ float sh_x[XCHUNK * NB];    // x[tt][n]
    __shared__ float sh_c[NB][HID];
    __shared__ float sh_hd[NB][128];

    // ---- resident A fragments (fp16, gate-major permuted) ----
    unsigned Afr[2][4][4];
    #pragma unroll
    for (int mt = 0; mt < 2; mt++) {
        const int rLo = (2 * mt) * HID + u;        // gate 2mt   row
        const int rHi = (2 * mt + 1) * HID + u;    // gate 2mt+1 row
        #pragma unroll
        for (int kt = 0; kt < 4; kt++) {
            const int c0 = 16 * kt + 2 * tig;
            Afr[mt][kt][0] = pack_h2(__ldg(W_hh + rLo * HID + c0),
                                     __ldg(W_hh + rLo * HID + c0 + 1));
            Afr[mt][kt][1] = pack_h2(__ldg(W_hh + rHi * HID + c0),
                                     __ldg(W_hh + rHi * HID + c0 + 1));
            Afr[mt][kt][2] = pack_h2(__ldg(W_hh + rLo * HID + c0 + 8),
                                     __ldg(W_hh + rLo * HID + c0 + 9));
            Afr[mt][kt][3] = pack_h2(__ldg(W_hh + rHi * HID + c0 + 8),
                                     __ldg(W_hh + rHi * HID + c0 + 9));
        }
    }
    float wih[4], bias[4];
    #pragma unroll
    for (int g = 0; g < 4; g++) {
        const int r = g * HID + u;
        wih[g]  = __ldg(W_ih + r);
        bias[g] = __ldg(b_ih + r) + __ldg(b_hh + r);
    }

    // writer word: batch n = 2tig + (gid&1), unit pair kp = w*4 + (gid>>1)
    const int woff = (2 * tig + (gid & 1)) * 36 + w * 4 + (gid >> 1);
    // reader base: n = gid row
    const int rbase = gid * 36 + tig;

    float c0r = 0.0f, c1r = 0.0f;   // cell state, batches 2tig / 2tig+1

    for (int idx = j; idx < 8 * 36; idx += 256) sh_H[0][idx] = 0u;
    __syncthreads();

    // ---- one LSTM step ----
    auto step = [&](const unsigned* __restrict__ Hin,
                    unsigned* __restrict__ Hout, int tt) {
        const float2 xv = *reinterpret_cast<const float2*>(&sh_x[tt * 8 + 2 * tig]);

        float d [2][4], d2[2][4];
        #pragma unroll
        for (int mt = 0; mt < 2; mt++) {
            d [mt][0] = fmaf(xv.x, wih[2 * mt],     bias[2 * mt]);
            d [mt][1] = fmaf(xv.y, wih[2 * mt],     bias[2 * mt]);
            d [mt][2] = fmaf(xv.x, wih[2 * mt + 1], bias[2 * mt + 1]);
            d [mt][3] = fmaf(xv.y, wih[2 * mt + 1], bias[2 * mt + 1]);
            d2[mt][0] = 0.0f; d2[mt][1] = 0.0f; d2[mt][2] = 0.0f; d2[mt][3] = 0.0f;
        }

        #pragma unroll
        for (int kt = 0; kt < 4; kt++) {
            const unsigned bf0 = Hin[rbase + 8 * kt];        // k = 2tig+16kt, +1
            const unsigned bf1 = Hin[rbase + 4 + 8 * kt];    // k = 2tig+8+16kt, +1
            float (*acc)[4] = (kt < 2) ? d : d2;
            mma_f16(acc[0][0], acc[0][1], acc[0][2], acc[0][3],
                    Afr[0][kt][0], Afr[0][kt][1], Afr[0][kt][2], Afr[0][kt][3],
                    bf0, bf1);
            mma_f16(acc[1][0], acc[1][1], acc[1][2], acc[1][3],
                    Afr[1][kt][0], Afr[1][kt][1], Afr[1][kt][2], Afr[1][kt][3],
                    bf0, bf1);
        }

        const float iv0 = sigA (d[0][0] + d2[0][0]);
        const float iv1 = sigA (d[0][1] + d2[0][1]);
        const float fv0 = sigA (d[0][2] + d2[0][2]);
        const float fv1 = sigA (d[0][3] + d2[0][3]);
        const float gv0 = tanhA(d[1][0] + d2[1][0]);
        const float gv1 = tanhA(d[1][1] + d2[1][1]);
        const float ov0 = sigA (d[1][2] + d2[1][2]);
        const float ov1 = sigA (d[1][3] + d2[1][3]);

        c0r = fmaf(fv0, c0r, iv0 * gv0);
        c1r = fmaf(fv1, c1r, iv1 * gv1);
        const float h0 = ov0 * tanhA(c0r);    // batch 2tig
        const float h1 = ov1 * tanhA(c1r);    // batch 2tig+1

        // unit-pair exchange: even gid writes batch 2tig word, odd gid writes
        // batch 2tig+1 word; partner (gid^1, lane^4) supplies the other unit.
        const float sendv = (gid & 1) ? h0 : h1;
        const float recv  = __shfl_xor_sync(0xffffffffu, sendv, 4);
        const unsigned hw = (gid & 1) ? pack_h2(recv, h1) : pack_h2(h0, recv);
        Hout[woff] = hw;
        __syncthreads();
    };

    // ---- time recurrence ----
    #pragma unroll 1
    for (int t0 = 0; t0 < SEQ; t0 += XCHUNK) {
        #pragma unroll
        for (int i = 0; i < (XCHUNK * NB) / 256; i++) {
            const int idx = j + i * 256;
            sh_x[idx] = __ldg(x + (t0 + (idx >> 3)) * BATCH + b0 + (idx & 7));
        }
        __syncthreads();

        #pragma unroll 1
        for (int tt = 0; tt < XCHUNK; tt += 2) {
            step(sh_H[0], sh_H[1], tt);
            step(sh_H[1], sh_H[0], tt + 1);
        }
    }

    // ---- MLP head on cell states (8 batches) ----
    sh_c[2 * tig][u]     = c0r;
    sh_c[2 * tig + 1][u] = c1r;
    __syncthreads();

    #pragma unroll
    for (int i = 0; i < 4; i++) {          // 8 batches x 128 rows = 1024 tasks
        const int t   = j + i * 256;
        const int row = t & 127;
        const int bt  = t >> 7;
        const float* fw = fc1_w + row * HID;
        float acc = __ldg(fc1_b + row);
        #pragma unroll
        for (int k = 0; k < HID; k++) acc = fmaf(__ldg(fw + k), sh_c[bt][k], acc);
        sh_hd[bt][row] = acc;
    }
    __syncthreads();

    if (j < NB * 5) {
        const int bt  = j / 5;
        const int row = j % 5;
        const float* fw = fc2_w + row * 128;
        float acc = __ldg(fc2_b + row);
        #pragma unroll
        for (int k = 0; k < 128; k++) acc = fmaf(__ldg(fw + k), sh_hd[bt][k], acc);
        out[(b0 + bt) * 5 + row] = acc;
    }
}

extern "C" void kernel_launch(void* const* d_in, const int* in_sizes, int n_in,
                              void* d_out, int out_size)
{
    const float* x     = (const float*)d_in[0];
    const float* W_ih  = (const float*)d_in[1];
    const float* W_hh  = (const float*)d_in[2];
    const float* b_ih  = (const float*)d_in[3];
    const float* b_hh  = (const float*)d_in[4];
    const float* fc1_w = (const float*)d_in[5];
    const float* fc1_b = (const float*)d_in[6];
    const float* fc2_w = (const float*)d_in[7];
    const float* fc2_b = (const float*)d_in[8];
    float* out = (float*)d_out;

    lstm_mma_kernel<<<BATCH / NB, 256>>>(x, W_ih, W_hh, b_ih, b_hh,
                                         fc1_w, fc1_b, fc2_w, fc2_b, out);
}